// round 17
// baseline (speedup 1.0000x reference)
#include <cuda_runtime.h>
#include <cuda_bf16.h>
#include <cstdint>

#define T_STEPS 64
#define N_NODES 20000
#define NTILES_TOT 1250     // 16 nodes per tile, 1 tile per active warp

__device__ float g_scratch[T_STEPS * NTILES_TOT];

__device__ __forceinline__ float tanha(float v) {
    float r; asm("tanh.approx.f32 %0, %1;" : "=f"(r) : "f"(v)); return r;
}
__device__ __forceinline__ float sigm(float v) { return fmaf(0.5f, tanha(0.5f * v), 0.5f); }
__device__ __forceinline__ float lrelu(float v) { return fmaxf(v, 0.01f * v); }
__device__ __forceinline__ uint32_t tf(float v) {
    uint32_t r; asm("cvt.rna.tf32.f32 %0, %1;" : "=r"(r) : "f"(v)); return r;
}
__device__ __forceinline__ void mmatf(float* c, const uint32_t* a, uint32_t b0, uint32_t b1) {
    asm volatile("mma.sync.aligned.m16n8k8.row.col.f32.tf32.tf32.f32 "
        "{%0,%1,%2,%3}, {%4,%5,%6,%7}, {%8,%9}, {%0,%1,%2,%3};"
        : "+f"(c[0]), "+f"(c[1]), "+f"(c[2]), "+f"(c[3])
        : "r"(a[0]), "r"(a[1]), "r"(a[2]), "r"(a[3]), "r"(b0), "r"(b1));
}

// tf32 weights in smem, conflict-free strides
__shared__ uint32_t sW1[96 * 44];   // [n=96][k=44]: k0-7 Wx*, k8-39 Wh{z,r} (cand rows 0)
__shared__ uint32_t sW2[32 * 36];   // [n=32][k=36]: Whh^T

// transpose C-layout pair registers -> tf32 A-fragment for one k8 block.
__device__ __forceinline__ void h2a(const float* v0, const float* v1, int B,
                                    int o1, int o2, bool ls, uint32_t* A) {
    float p00 = __shfl_sync(0xffffffffu, v0[2*B],   o1);
    float p01 = __shfl_sync(0xffffffffu, v0[2*B+1], o1);
    float p10 = __shfl_sync(0xffffffffu, v1[2*B],   o1);
    float p11 = __shfl_sync(0xffffffffu, v1[2*B+1], o1);
    float q00 = __shfl_sync(0xffffffffu, v0[2*B],   o2);
    float q01 = __shfl_sync(0xffffffffu, v0[2*B+1], o2);
    float q10 = __shfl_sync(0xffffffffu, v1[2*B],   o2);
    float q11 = __shfl_sync(0xffffffffu, v1[2*B+1], o2);
    A[0] = tf(ls ? p01 : p00);
    A[1] = tf(ls ? p11 : p10);
    A[2] = tf(ls ? q01 : q00);
    A[3] = tf(ls ? q11 : q10);
}

__device__ void run_tile(int tile,
    const float* __restrict__ x, const float* __restrict__ h0,
    const float* __restrict__ W1, float b1s, const float* __restrict__ W2,
    const float* __restrict__ bxz, const float* __restrict__ bhz,
    const float* __restrict__ bxr, const float* __restrict__ bhr,
    const float* __restrict__ bxh, const float* __restrict__ bhh,
    float* __restrict__ out, int out_size, int lane)
{
    const int l = lane & 3, g = lane >> 2;
    const int o1 = (lane & 28) | (l >> 1), o2 = o1 + 2;
    const bool ls = l & 1;

    float w1s[8];
#pragma unroll
    for (int s = 0; s < 8; s++) w1s[s] = W1[2 * l + 8 * (s >> 1) + (s & 1)];

    float bC[12][2];
#pragma unroll
    for (int jj = 0; jj < 4; jj++)
#pragma unroll
        for (int e = 0; e < 2; e++) {
            int n = 8 * jj + 2 * l + e;
            bC[jj][e]     = bxz[n] + bhz[n];
            bC[jj + 4][e] = bxr[n] + bhr[n];
            bC[jj + 8][e] = bxh[n] + bhh[n];
        }

    // preload weight B-fragments: MMA1 x-chunks (12j x 2) + MMA2 (4j x 4c x 2)
    uint32_t w1x[12][2], w2f[4][4][2];
#pragma unroll
    for (int j = 0; j < 12; j++) {
        const uint32_t* wr = &sW1[(8 * j + g) * 44];
        w1x[j][0] = wr[l]; w1x[j][1] = wr[l + 4];
    }
#pragma unroll
    for (int j = 0; j < 4; j++) {
        const uint32_t* wr = &sW2[(8 * j + g) * 36];
#pragma unroll
        for (int c = 0; c < 4; c++) {
            w2f[j][c][0] = wr[8 * c + l]; w2f[j][c][1] = wr[8 * c + l + 4];
        }
    }

    const int n0 = tile * 16 + g;
    const int n1 = n0 + 8;
    float h[2][8];
#pragma unroll
    for (int s = 0; s < 8; s++) {
        int d = 2 * l + 8 * (s >> 1) + (s & 1);
        h[0][s] = h0[n0 * 32 + d];
        h[1][s] = h0[n1 * 32 + d];
    }
    const float w2a = W2[n0], w2b = W2[n1];

    // x for t=0
    float xc0 = x[(size_t)n0 * 8 + l],     xc1 = x[(size_t)n1 * 8 + l];
    float xc2 = x[(size_t)n0 * 8 + l + 4], xc3 = x[(size_t)n1 * 8 + l + 4];

#pragma unroll 1
    for (int t = 0; t < T_STEPS; ++t) {
        // ---- prefetch x for t+1 (latency overlaps entire step body) ----
        float xn0 = 0.f, xn1 = 0.f, xn2 = 0.f, xn3 = 0.f;
        if (t + 1 < T_STEPS) {
            const float* xb1 = x + (size_t)(t + 1) * (N_NODES * 8);
            xn0 = xb1[(size_t)n0 * 8 + l];     xn1 = xb1[(size_t)n1 * 8 + l];
            xn2 = xb1[(size_t)n0 * 8 + l + 4]; xn3 = xb1[(size_t)n1 * 8 + l + 4];
        }
        uint32_t Ax[4] = {tf(xc0), tf(xc1), tf(xc2), tf(xc3)};
        // ---- h A-fragments (4 k8 chunks) via shuffle transpose ----
        uint32_t Ah[4][4];
#pragma unroll
        for (int B = 0; B < 4; B++) h2a(h[0], h[1], B, o1, o2, ls, Ah[B]);

        // ---- MMA1: 12 n-tiles, single-pass tf32 ----
        float zz[2][8], gg[2][8], candC[4][4];
#pragma unroll
        for (int j = 0; j < 12; j++) {
            float C[4] = {bC[j][0], bC[j][1], bC[j][0], bC[j][1]};
            mmatf(C, Ax, w1x[j][0], w1x[j][1]);
            if (j < 8) {
                const uint32_t* wr = &sW1[(8 * j + g) * 44];
#pragma unroll
                for (int c = 0; c < 4; c++)
                    mmatf(C, Ah[c], wr[8 + 8 * c + l], wr[8 + 8 * c + l + 4]);
            }
            if (j < 4) {
                zz[0][2*j] = sigm(C[0]); zz[0][2*j+1] = sigm(C[1]);
                zz[1][2*j] = sigm(C[2]); zz[1][2*j+1] = sigm(C[3]);
            } else if (j < 8) {
                int jj = j - 4;
                gg[0][2*jj]   = h[0][2*jj]   * sigm(C[0]);
                gg[0][2*jj+1] = h[0][2*jj+1] * sigm(C[1]);
                gg[1][2*jj]   = h[1][2*jj]   * sigm(C[2]);
                gg[1][2*jj+1] = h[1][2*jj+1] * sigm(C[3]);
            } else {
#pragma unroll
                for (int e = 0; e < 4; e++) candC[j - 8][e] = C[e];
            }
        }

        // ---- gg -> A-fragments, MMA2 into candC (weights in regs) ----
        uint32_t Ag[4][4];
#pragma unroll
        for (int B = 0; B < 4; B++) h2a(gg[0], gg[1], B, o1, o2, ls, Ag[B]);
#pragma unroll
        for (int j = 0; j < 4; j++)
#pragma unroll
            for (int c = 0; c < 4; c++)
                mmatf(candC[j], Ag[c], w2f[j][c][0], w2f[j][c][1]);

        // ---- update + fused readout ----
        float p0 = 0.f, p1 = 0.f;
#pragma unroll
        for (int j = 0; j < 4; j++) {
            float t00 = tanha(candC[j][0]), t01 = tanha(candC[j][1]);
            float t10 = tanha(candC[j][2]), t11 = tanha(candC[j][3]);
            float hn;
            hn = t00 + zz[0][2*j]   * (h[0][2*j]   - t00); h[0][2*j]   = hn; p0 = fmaf(lrelu(hn), w1s[2*j],   p0);
            hn = t01 + zz[0][2*j+1] * (h[0][2*j+1] - t01); h[0][2*j+1] = hn; p0 = fmaf(lrelu(hn), w1s[2*j+1], p0);
            hn = t10 + zz[1][2*j]   * (h[1][2*j]   - t10); h[1][2*j]   = hn; p1 = fmaf(lrelu(hn), w1s[2*j],   p1);
            hn = t11 + zz[1][2*j+1] * (h[1][2*j+1] - t11); h[1][2*j+1] = hn; p1 = fmaf(lrelu(hn), w1s[2*j+1], p1);
        }
        p0 += __shfl_xor_sync(0xffffffffu, p0, 1);
        p0 += __shfl_xor_sync(0xffffffffu, p0, 2);
        p1 += __shfl_xor_sync(0xffffffffu, p1, 1);
        p1 += __shfl_xor_sync(0xffffffffu, p1, 2);
        float st = lrelu(p0 + b1s) * w2a + lrelu(p1 + b1s) * w2b;
        st += __shfl_xor_sync(0xffffffffu, st, 4);
        st += __shfl_xor_sync(0xffffffffu, st, 8);
        st += __shfl_xor_sync(0xffffffffu, st, 16);
        if (lane == 0) g_scratch[t * NTILES_TOT + tile] = st;

        xc0 = xn0; xc1 = xn1; xc2 = xn2; xc3 = xn3;
    }

    if (out_size >= N_NODES * 32) {
        const int hoff = out_size - N_NODES * 32;
#pragma unroll
        for (int j = 0; j < 4; j++) {
            *(float2*)(out + hoff + n0 * 32 + 2 * l + 8 * j) = make_float2(h[0][2*j], h[0][2*j+1]);
            *(float2*)(out + hoff + n1 * 32 + 2 * l + 8 * j) = make_float2(h[1][2*j], h[1][2*j+1]);
        }
    }
}

__global__ void __launch_bounds__(320, 1)
gru_mma(const float* __restrict__ x, const float* __restrict__ h0,
        const float* __restrict__ Wxz, const float* __restrict__ bxz,
        const float* __restrict__ Whz, const float* __restrict__ bhz,
        const float* __restrict__ Wxr, const float* __restrict__ bxr,
        const float* __restrict__ Whr, const float* __restrict__ bhr,
        const float* __restrict__ Wxh, const float* __restrict__ bxh,
        const float* __restrict__ Whh, const float* __restrict__ bhh,
        const float* __restrict__ W1,  const float* __restrict__ b1,
        const float* __restrict__ W2,
        float* __restrict__ out, int out_size)
{
    const int tid = threadIdx.x, b = blockIdx.x;
    for (int i = tid; i < 96 * 44; i += 320) {
        int n = i / 44, k = i % 44;
        float v = 0.f;
        if (k < 8) v = (n < 32) ? Wxz[k*32+n] : (n < 64) ? Wxr[k*32+n-32] : Wxh[k*32+n-64];
        else if (k < 40) {
            int kk = k - 8;
            v = (n < 32) ? Whz[kk*32+n] : (n < 64) ? Whr[kk*32+n-32] : 0.f;
        }
        sW1[i] = tf(v);
    }
    for (int i = tid; i < 32 * 36; i += 320) {
        int n = i / 36, k = i % 36;
        sW2[i] = tf((k < 32) ? Whh[k*32+n] : 0.f);
    }
    __syncthreads();

    const int w = tid >> 5, lane = tid & 31;
    const float b1s = b1[0];

    const int nact = (b < 66) ? 9 : 8;
    if (w < nact) {
        const int tile = (b < 66) ? (9 * b + w) : (594 + 8 * (b - 66) + w);
        run_tile(tile, x, h0, W1, b1s, W2, bxz, bhz, bxr, bhr, bxh, bhh,
                 out, out_size, lane);
    }
}

__global__ void __launch_bounds__(1024, 1)
reduce_out(const float* __restrict__ b2, float* __restrict__ out, int out_size)
{
    const int t = blockIdx.x;
    float s = 0.f;
    for (int w = threadIdx.x; w < NTILES_TOT; w += 1024) s += g_scratch[t * NTILES_TOT + w];
#pragma unroll
    for (int o = 16; o; o >>= 1) s += __shfl_xor_sync(0xffffffffu, s, o);
    __shared__ float red[32];
    if ((threadIdx.x & 31) == 0) red[threadIdx.x >> 5] = s;
    __syncthreads();
    if (threadIdx.x < 32) {
        s = red[threadIdx.x];
#pragma unroll
        for (int o = 16; o; o >>= 1) s += __shfl_xor_sync(0xffffffffu, s, o);
        if (threadIdx.x == 0) {
            bool wr = (out_size >= T_STEPS + N_NODES * 32) || (out_size < N_NODES * 32);
            if (wr && t < out_size) out[t] = s + b2[0];
        }
    }
}

extern "C" void kernel_launch(void* const* d_in, const int* in_sizes, int n_in,
                              void* d_out, int out_size) {
    const float* x   = (const float*)d_in[0];
    const float* h0  = (const float*)d_in[3];
    const float* Wxz = (const float*)d_in[4];
    const float* bxz = (const float*)d_in[5];
    const float* Whz = (const float*)d_in[6];
    const float* bhz = (const float*)d_in[7];
    const float* Wxr = (const float*)d_in[8];
    const float* bxr = (const float*)d_in[9];
    const float* Whr = (const float*)d_in[10];
    const float* bhr = (const float*)d_in[11];
    const float* Wxh = (const float*)d_in[12];
    const float* bxh = (const float*)d_in[13];
    const float* Whh = (const float*)d_in[14];
    const float* bhh = (const float*)d_in[15];
    const float* W1  = (const float*)d_in[16];
    const float* b1  = (const float*)d_in[17];
    const float* W2  = (const float*)d_in[18];
    const float* b2  = (const float*)d_in[19];
    float* out = (float*)d_out;

    gru_mma<<<148, 320>>>(x, h0, Wxz, bxz, Whz, bhz, Wxr, bxr, Whr, bhr,
                          Wxh, bxh, Whh, bhh, W1, b1, W2, out, out_size);
    reduce_out<<<T_STEPS, 1024>>>(b2, out, out_size);
}